// round 13
// baseline (speedup 1.0000x reference)
#include <cuda_runtime.h>
#include <cuda_bf16.h>
#include <cuda_fp16.h>
#include <cstdint>

#define NN 50000
#define NE 1250000
#define LF 64
#define HF 128
#define NSTEP 5
#define EPSV 1e-6f
#define NBLK 196   // ceil(NN/256)

// ---------------- device scratch (static: no allocations allowed) -------------
__device__ __half g_e[(size_t)NE * LF];  // encoded edges, RECEIVER-SORTED, fp16
__device__ int    g_eid[NE];             // sorted slot -> edge id (scatter order)
__device__ int    g_send[NE];            // sender per sorted slot
__device__ int    g_off[NN + 1];
__device__ int    g_cnt[NN];
__device__ int    g_cur[NN];
__device__ int    g_bsum[256];
__device__ unsigned int g_wq[8];         // per-step work-steal counters
__device__ float  g_n[NN * LF];
__device__ float  g_x[NN * LF];

// split-precision fp16 weight fragments, hi/lo interleaved as uint4 {h0,h1,l0,l1}
__device__ uint4 g_fB0[8][4][16][32];   // layer1: K pad 64, N=128 (FIN=64 MLPs)
__device__ uint4 g_fB1[8][8][16][32];   // layer2: K=128, N=128
__device__ uint4 g_fB2[8][8][8][32];    // layer3: K=128, N pad 64
__device__ float g_b0[8][128], g_b1[8][128], g_b2[8][64];

struct WPtrs { const float* p[48]; };

// ---------------- helpers ------------------------------------------------------
// fp16 hi/lo split: residual after 11-bit hi is ~2^-22 -> 3-term MMA ~fp32-exact
__device__ __forceinline__ void split_pack(float v0, float v1, uint32_t& h, uint32_t& l) {
    __half2 hp = __floats2half2_rn(v0, v1);
    float2 hf = __half22float2(hp);
    __half2 lp = __floats2half2_rn(v0 - hf.x, v1 - hf.y);
    h = *(uint32_t*)&hp;
    l = *(uint32_t*)&lp;
}

__device__ __forceinline__ void mma16816(float* c, const uint32_t* a, uint32_t b0, uint32_t b1) {
    asm volatile(
        "mma.sync.aligned.m16n8k16.row.col.f32.f16.f16.f32 "
        "{%0,%1,%2,%3}, {%4,%5,%6,%7}, {%8,%9}, {%0,%1,%2,%3};"
        : "+f"(c[0]), "+f"(c[1]), "+f"(c[2]), "+f"(c[3])
        : "r"(a[0]), "r"(a[1]), "r"(a[2]), "r"(a[3]), "r"(b0), "r"(b1));
}

// 3-term split MMA: C += Ah*Bh + Ah*Bl + Al*Bh  (~fp32-exact)
__device__ __forceinline__ void mma3(float* c, const uint32_t* ah, const uint32_t* al, uint4 b) {
    mma16816(c, ah, b.x, b.y);
    mma16816(c, ah, b.z, b.w);
    mma16816(c, al, b.x, b.y);
}
// 2-term split MMA: C += Ah*Bh + Ah*Bl  (drops Al*Bh — edge encoder only,
// whose output is fp16-quantized (2^-11) anyway)
__device__ __forceinline__ void mma2(float* c, const uint32_t* ah, uint4 b) {
    mma16816(c, ah, b.x, b.y);
    mma16816(c, ah, b.z, b.w);
}

// ---------------- weight fragment + bias prep (single kernel) ------------------
__global__ void k_prep(WPtrs P) {
    const int L = blockIdx.y;
    if (L == 3) {
        for (int idx = blockIdx.x * 256 + threadIdx.x; idx < 16 * 128 + 8 * 64; idx += gridDim.x * 256) {
            if (idx < 8 * 128) {
                int m = idx >> 7, j = idx & 127;
                g_b0[m][j] = P.p[24 + m * 3 + 0][j];
            } else if (idx < 16 * 128) {
                int t = idx - 1024;
                int m = t >> 7, j = t & 127;
                g_b1[m][j] = P.p[24 + m * 3 + 1][j];
            } else {
                int t = idx - 2048;
                int m = t >> 6, j = t & 63;
                int Nr = (m == 7) ? 2 : 64;
                g_b2[m][j] = (j < Nr) ? P.p[24 + m * 3 + 2][j] : 0.f;
            }
        }
        return;
    }
    const int KT = (L == 0) ? 4 : 8;
    const int NT = (L == 2) ? 8 : 16;
    const int total = 8 * KT * NT * 32;
    for (int idx = blockIdx.x * 256 + threadIdx.x; idx < total; idx += gridDim.x * 256) {
        int lane = idx & 31;
        int r = idx >> 5;
        int nt = r % NT; r /= NT;
        int kt = r % KT;
        int m = r / KT;
        int K = (L == 0) ? (m == 0 ? 2 : (m == 1 ? 3 : 64)) : 128;
        int N = (L == 2) ? (m == 7 ? 2 : 64) : 128;
        const float* W = P.p[m * 3 + L];
        int k0 = kt * 16 + 2 * (lane & 3);
        int n  = nt * 8 + (lane >> 2);
        float v[4];
        #pragma unroll
        for (int j = 0; j < 4; j++) {
            int k = k0 + (j >> 1) * 8 + (j & 1);
            v[j] = (k < K && n < N) ? W[k * N + n] : 0.f;
        }
        uint32_t h0, l0, h1, l1;
        split_pack(v[0], v[1], h0, l0);
        split_pack(v[2], v[3], h1, l1);
        uint4 f = make_uint4(h0, h1, l0, l1);
        if (L == 0)      g_fB0[m][kt][nt][lane] = f;
        else if (L == 1) g_fB1[m][kt][nt][lane] = f;
        else             g_fB2[m][kt][nt][lane] = f;
    }
}

// ---------------- fused 3-layer MLP, register-resident mma.sync ----------------
// 384 threads = 12 warps, tile = 192 rows (16 per warp).
// FIN<=4: layer 1 scalar fp32 (exact). EHALF: write output as fp16 to g_e.
// TWO: 2-term split on layers 2/3 (edge encoder only; output fp16 anyway).
template <int FIN, int NT3, bool GATHER, bool MASK, bool EHALF, bool TWO>
__global__ void __launch_bounds__(384, 1) k_mlp_tc(
    int mlp, const float* __restrict__ xin, int nrows, int ntiles,
    float* __restrict__ out, const float* __restrict__ msrc,
    const float* __restrict__ W0raw, const float* __restrict__ b0raw)
{
    constexpr bool SC1 = (FIN <= 4);
    extern __shared__ char smraw[];
    char* pp = smraw;
    float* sw0 = nullptr;
    uint4* s0 = nullptr;
    if constexpr (SC1) { sw0 = (float*)pp; pp += FIN * 128 * sizeof(float); }
    else { s0 = (uint4*)pp; pp += 4 * 16 * 32 * sizeof(uint4); }
    uint4* s1 = (uint4*)pp; pp += 8 * 16 * 32 * sizeof(uint4);
    uint4* s2 = (uint4*)pp; pp += 8 * NT3 * 32 * sizeof(uint4);
    float* sb0 = (float*)pp; pp += 128 * sizeof(float);
    float* sb1 = (float*)pp; pp += 128 * sizeof(float);
    float* sb2 = (float*)pp;

    const int tid = threadIdx.x;
    {
        if constexpr (SC1) {
            for (int i = tid; i < FIN * 128; i += 384) sw0[i] = __ldg(W0raw + i);
            if (tid < 128) sb0[tid] = __ldg(b0raw + tid);
        } else {
            const uint4* f0 = (const uint4*)g_fB0[mlp];
            for (int i = tid; i < 4 * 16 * 32; i += 384) s0[i] = f0[i];
            if (tid < 128) sb0[tid] = g_b0[mlp][tid];
        }
        const uint4* f1 = (const uint4*)g_fB1[mlp];
        for (int i = tid; i < 8 * 16 * 32; i += 384) s1[i] = f1[i];
        for (int i = tid; i < 8 * NT3 * 32; i += 384) {
            int lane = i & 31, t = i >> 5;
            int nt = t % NT3, kt = t / NT3;
            s2[i] = g_fB2[mlp][kt][nt][lane];
        }
        if (tid >= 128 && tid < 256) sb1[tid - 128] = g_b1[mlp][tid - 128];
        if (tid >= 256 && tid < 320) sb2[tid - 256] = g_b2[mlp][tid - 256];
    }
    __syncthreads();

    const int lane = tid & 31, w = tid >> 5;
    const int lr  = lane >> 2;
    const int lc2 = 2 * (lane & 3);

    for (int tile = blockIdx.x; tile < ntiles; tile += gridDim.x) {
        const int r0 = tile * 192 + w * 16 + lr;
        const int r1 = r0 + 8;

        float C1[16][4];
        #pragma unroll
        for (int nt = 0; nt < 16; nt++) {
            float2 b = *(const float2*)&sb0[nt * 8 + lc2];
            C1[nt][0] = b.x; C1[nt][1] = b.y; C1[nt][2] = b.x; C1[nt][3] = b.y;
        }

        if constexpr (SC1) {
            float x0[FIN], x1[FIN];
            #pragma unroll
            for (int k = 0; k < FIN; k++) { x0[k] = 0.f; x1[k] = 0.f; }
            if (r0 < nrows) {
                int s = GATHER ? __ldg(&g_eid[r0]) : r0;
                #pragma unroll
                for (int k = 0; k < FIN; k++) x0[k] = __ldg(xin + (size_t)s * FIN + k);
            }
            if (r1 < nrows) {
                int s = GATHER ? __ldg(&g_eid[r1]) : r1;
                #pragma unroll
                for (int k = 0; k < FIN; k++) x1[k] = __ldg(xin + (size_t)s * FIN + k);
            }
            #pragma unroll
            for (int nt = 0; nt < 16; nt++) {
                int c = nt * 8 + lc2;
                #pragma unroll
                for (int k = 0; k < FIN; k++) {
                    float2 wv = *(const float2*)&sw0[k * 128 + c];
                    C1[nt][0] = fmaf(x0[k], wv.x, C1[nt][0]);
                    C1[nt][1] = fmaf(x0[k], wv.y, C1[nt][1]);
                    C1[nt][2] = fmaf(x1[k], wv.x, C1[nt][2]);
                    C1[nt][3] = fmaf(x1[k], wv.y, C1[nt][3]);
                }
            }
        } else {
            uint32_t a1h[4][4], a1l[4][4];
            const float* x0 = (r0 < nrows) ? xin + (size_t)r0 * 64 : nullptr;
            const float* x1 = (r1 < nrows) ? xin + (size_t)r1 * 64 : nullptr;
            #pragma unroll
            for (int kt = 0; kt < 4; kt++) {
                int ks = kt * 16 + lc2;
                float2 p00 = x0 ? *(const float2*)(x0 + ks)     : make_float2(0.f, 0.f);
                float2 p10 = x1 ? *(const float2*)(x1 + ks)     : make_float2(0.f, 0.f);
                float2 p01 = x0 ? *(const float2*)(x0 + ks + 8) : make_float2(0.f, 0.f);
                float2 p11 = x1 ? *(const float2*)(x1 + ks + 8) : make_float2(0.f, 0.f);
                split_pack(p00.x, p00.y, a1h[kt][0], a1l[kt][0]);
                split_pack(p10.x, p10.y, a1h[kt][1], a1l[kt][1]);
                split_pack(p01.x, p01.y, a1h[kt][2], a1l[kt][2]);
                split_pack(p11.x, p11.y, a1h[kt][3], a1l[kt][3]);
            }
            #pragma unroll
            for (int kt = 0; kt < 4; kt++) {
                #pragma unroll
                for (int nt = 0; nt < 16; nt++)
                    mma3(C1[nt], a1h[kt], a1l[kt], s0[(kt * 16 + nt) * 32 + lane]);
            }
        }

        // ---- relu + split -> layer-2 A fragments ----
        uint32_t a2h[8][4], a2l[8][4];
        #pragma unroll
        for (int nt = 0; nt < 16; nt++) {
            float c0 = fmaxf(C1[nt][0], 0.f), c1 = fmaxf(C1[nt][1], 0.f);
            float c2 = fmaxf(C1[nt][2], 0.f), c3 = fmaxf(C1[nt][3], 0.f);
            int j = nt >> 1, o = (nt & 1) * 2;
            split_pack(c0, c1, a2h[j][o],     a2l[j][o]);
            split_pack(c2, c3, a2h[j][o + 1], a2l[j][o + 1]);
        }

        // ---- layer 2 ----
        float C2[16][4];
        #pragma unroll
        for (int nt = 0; nt < 16; nt++) {
            float2 b = *(const float2*)&sb1[nt * 8 + lc2];
            C2[nt][0] = b.x; C2[nt][1] = b.y; C2[nt][2] = b.x; C2[nt][3] = b.y;
        }
        #pragma unroll
        for (int kt = 0; kt < 8; kt++) {
            #pragma unroll
            for (int nt = 0; nt < 16; nt++) {
                if constexpr (TWO) mma2(C2[nt], a2h[kt], s1[(kt * 16 + nt) * 32 + lane]);
                else               mma3(C2[nt], a2h[kt], a2l[kt], s1[(kt * 16 + nt) * 32 + lane]);
            }
        }

        // ---- relu + split -> layer-3 A fragments ----
        uint32_t a3h[8][4], a3l[8][4];
        #pragma unroll
        for (int nt = 0; nt < 16; nt++) {
            float c0 = fmaxf(C2[nt][0], 0.f), c1 = fmaxf(C2[nt][1], 0.f);
            float c2 = fmaxf(C2[nt][2], 0.f), c3 = fmaxf(C2[nt][3], 0.f);
            int j = nt >> 1, o = (nt & 1) * 2;
            if constexpr (TWO) {
                __half2 hp = __floats2half2_rn(c0, c1);
                a3h[j][o] = *(uint32_t*)&hp;
                __half2 hp2 = __floats2half2_rn(c2, c3);
                a3h[j][o + 1] = *(uint32_t*)&hp2;
            } else {
                split_pack(c0, c1, a3h[j][o],     a3l[j][o]);
                split_pack(c2, c3, a3h[j][o + 1], a3l[j][o + 1]);
            }
        }

        // ---- layer 3 (linear) ----
        float C3[NT3][4];
        #pragma unroll
        for (int nt = 0; nt < NT3; nt++) {
            float2 b = *(const float2*)&sb2[nt * 8 + lc2];
            C3[nt][0] = b.x; C3[nt][1] = b.y; C3[nt][2] = b.x; C3[nt][3] = b.y;
        }
        #pragma unroll
        for (int kt = 0; kt < 8; kt++) {
            #pragma unroll
            for (int nt = 0; nt < NT3; nt++) {
                if constexpr (TWO) mma2(C3[nt], a3h[kt], s2[(kt * NT3 + nt) * 32 + lane]);
                else               mma3(C3[nt], a3h[kt], a3l[kt], s2[(kt * NT3 + nt) * 32 + lane]);
            }
        }

        // ---- store ----
        if constexpr (EHALF) {
            #pragma unroll
            for (int nt = 0; nt < 8; nt++) {
                int ci = nt * 4 + (lane & 3);
                if (r0 < nrows)
                    *(__half2*)&g_e[(size_t)r0 * 64 + 2 * ci] = __floats2half2_rn(C3[nt][0], C3[nt][1]);
                if (r1 < nrows)
                    *(__half2*)&g_e[(size_t)r1 * 64 + 2 * ci] = __floats2half2_rn(C3[nt][2], C3[nt][3]);
            }
        } else if (NT3 == 8) {
            #pragma unroll
            for (int nt = 0; nt < 8; nt++) {
                if (r0 < nrows) *(float2*)&out[(size_t)r0 * 64 + nt * 8 + lc2] = make_float2(C3[nt][0], C3[nt][1]);
                if (r1 < nrows) *(float2*)&out[(size_t)r1 * 64 + nt * 8 + lc2] = make_float2(C3[nt][2], C3[nt][3]);
            }
        } else {  // FOUT = 2 decoder
            if ((lane & 3) == 0) {
                if (r0 < nrows) {
                    float m0 = 1.f;
                    if (MASK) {
                        float2 nv = *(const float2*)&msrc[(size_t)r0 * 2];
                        m0 = ((fabsf(nv.x) + fabsf(nv.y)) != 0.f) ? 1.f : 0.f;
                    }
                    *(float2*)&out[(size_t)r0 * 2] = make_float2(C3[0][0] * m0, C3[0][1] * m0);
                }
                if (r1 < nrows) {
                    float m1 = 1.f;
                    if (MASK) {
                        float2 nv = *(const float2*)&msrc[(size_t)r1 * 2];
                        m1 = ((fabsf(nv.x) + fabsf(nv.y)) != 0.f) ? 1.f : 0.f;
                    }
                    *(float2*)&out[(size_t)r1 * 2] = make_float2(C3[0][2] * m1, C3[0][3] * m1);
                }
            }
        }
    }
}

constexpr int smem_bytes(int FIN, int NT3) {
    return ((FIN <= 4) ? (FIN * 128 * 4) : (4 * 16 * 32 * 16))
         + (8 * 16 * 32 + 8 * NT3 * 32) * 16
         + (128 + 128 + 64) * 4;
}

// ---------------- CSR build ----------------------------------------------------
__global__ void k_hist(const int* __restrict__ recv) {
    int i = blockIdx.x * blockDim.x + threadIdx.x;
    if (i < NE) atomicAdd(&g_cnt[recv[i]], 1);
}
__global__ void k_scan1() {
    __shared__ int s[256];
    int t = threadIdx.x;
    int i = blockIdx.x * 256 + t;
    int v = (i < NN) ? g_cnt[i] : 0;
    s[t] = v;
    __syncthreads();
    #pragma unroll
    for (int d = 1; d < 256; d <<= 1) {
        int y = (t >= d) ? s[t - d] : 0;
        __syncthreads();
        s[t] += y;
        __syncthreads();
    }
    if (i < NN) g_off[i] = s[t] - v;
    if (t == 255) g_bsum[blockIdx.x] = s[255];
}
__global__ void k_scan2() {
    __shared__ int s[256];
    int t = threadIdx.x;
    int v = (t < NBLK) ? g_bsum[t] : 0;
    s[t] = v;
    __syncthreads();
    #pragma unroll
    for (int d = 1; d < 256; d <<= 1) {
        int y = (t >= d) ? s[t - d] : 0;
        __syncthreads();
        s[t] += y;
        __syncthreads();
    }
    if (t < NBLK) g_bsum[t] = s[t] - v;
    if (t == 255) g_off[NN] = s[255];
}
__global__ void k_scan3() {
    int i = blockIdx.x * 256 + threadIdx.x;
    if (i < NN) {
        int o = g_off[i] + g_bsum[i >> 8];
        g_off[i] = o;
        g_cur[i] = o;
    }
}
// scatter fills g_send directly (no per-segment sort: intra-segment order
// only perturbs FP summation order, ~ulp-level output variation)
__global__ void k_scatter(const int* __restrict__ recv, const int* __restrict__ senders) {
    int i = blockIdx.x * blockDim.x + threadIdx.x;
    if (i < NE) {
        int p = atomicAdd(&g_cur[recv[i]], 1);
        g_eid[p] = i;
        g_send[p] = senders[i];
    }
}

// ---------------- GEN message + softmax aggregation ---------------------------
// Persistent + dynamic work-stealing: one warp grabs one receiver at a time via
// a per-step atomic counter -> no warp idles behind a high-degree sibling.
// 4-wide pipelined inner loop (MLP=8). Per-receiver output independent of
// assignment -> deterministic.
__global__ void __launch_bounds__(256) k_message(int step) {
    int lane = threadIdx.x & 31;
    const int fo = 2 * lane;

    for (;;) {
        unsigned int r;
        if (lane == 0) r = atomicAdd(&g_wq[step], 1u);
        r = __shfl_sync(0xFFFFFFFFu, r, 0);
        if (r >= NN) break;

        int o = g_off[r], e = g_off[r + 1];
        float S0 = 0.f, S1 = 0.f, W0 = 0.f, W1 = 0.f;

        int p = o;
        for (; p + 4 <= e; p += 4) {
            int s0 = __ldg(&g_send[p]);
            int s1 = __ldg(&g_send[p + 1]);
            int s2 = __ldg(&g_send[p + 2]);
            int s3 = __ldg(&g_send[p + 3]);
            __half2 e0 = __ldg((const __half2*)&g_e[(size_t)(p)     * 64 + fo]);
            __half2 e1 = __ldg((const __half2*)&g_e[(size_t)(p + 1) * 64 + fo]);
            __half2 e2 = __ldg((const __half2*)&g_e[(size_t)(p + 2) * 64 + fo]);
            __half2 e3 = __ldg((const __half2*)&g_e[(size_t)(p + 3) * 64 + fo]);
            float2 n0 = __ldg((const float2*)&g_n[(size_t)s0 * 64 + fo]);
            float2 n1 = __ldg((const float2*)&g_n[(size_t)s1 * 64 + fo]);
            float2 n2 = __ldg((const float2*)&g_n[(size_t)s2 * 64 + fo]);
            float2 n3 = __ldg((const float2*)&g_n[(size_t)s3 * 64 + fo]);

            float2 f0 = __half22float2(e0), f1 = __half22float2(e1);
            float2 f2 = __half22float2(e2), f3 = __half22float2(e3);
            float ma0 = fmaxf(n0.x + f0.x, 0.f) + EPSV, mb0 = fmaxf(n0.y + f0.y, 0.f) + EPSV;
            float ma1 = fmaxf(n1.x + f1.x, 0.f) + EPSV, mb1 = fmaxf(n1.y + f1.y, 0.f) + EPSV;
            float ma2 = fmaxf(n2.x + f2.x, 0.f) + EPSV, mb2 = fmaxf(n2.y + f2.y, 0.f) + EPSV;
            float ma3 = fmaxf(n3.x + f3.x, 0.f) + EPSV, mb3 = fmaxf(n3.y + f3.y, 0.f) + EPSV;
            float ta0 = __expf(ma0), tb0 = __expf(mb0);
            float ta1 = __expf(ma1), tb1 = __expf(mb1);
            float ta2 = __expf(ma2), tb2 = __expf(mb2);
            float ta3 = __expf(ma3), tb3 = __expf(mb3);
            S0 += (ta0 + ta1) + (ta2 + ta3);
            S1 += (tb0 + tb1) + (tb2 + tb3);
            W0 += fmaf(ta0, ma0, ta1 * ma1) + fmaf(ta2, ma2, ta3 * ma3);
            W1 += fmaf(tb0, mb0, tb1 * mb1) + fmaf(tb2, mb2, tb3 * mb3);
        }
        for (; p < e; p++) {
            int s = __ldg(&g_send[p]);
            __half2 eh = __ldg((const __half2*)&g_e[(size_t)p * 64 + fo]);
            float2 nv = __ldg((const float2*)&g_n[(size_t)s * 64 + fo]);
            float2 ec = __half22float2(eh);
            float m0 = fmaxf(nv.x + ec.x, 0.f) + EPSV;
            float m1 = fmaxf(nv.y + ec.y, 0.f) + EPSV;
            float t0 = __expf(m0);
            float t1 = __expf(m1);
            S0 += t0; W0 = fmaf(t0, m0, W0);
            S1 += t1; W1 = fmaf(t1, m1, W1);
        }

        float2 ns = *(const float2*)&g_n[(size_t)r * 64 + fo];
        float a0 = (e > o) ? (W0 / S0) : 0.f;
        float a1 = (e > o) ? (W1 / S1) : 0.f;
        *(float2*)&g_x[(size_t)r * 64 + fo] = make_float2(ns.x + a0, ns.y + a1);
    }
}

// ---------------- host launcher ------------------------------------------------
extern "C" void kernel_launch(void* const* d_in, const int* in_sizes, int n_in,
                              void* d_out, int out_size) {
    (void)in_sizes; (void)n_in; (void)out_size;

    const float* nodes     = (const float*)d_in[0];
    const float* edges     = (const float*)d_in[1];
    const int*   senders   = (const int*)d_in[2];
    const int*   receivers = (const int*)d_in[3];
    float* out = (float*)d_out;

    WPtrs P;
    P.p[0] = (const float*)d_in[4];  P.p[24 + 0] = (const float*)d_in[5];
    P.p[1] = (const float*)d_in[6];  P.p[24 + 1] = (const float*)d_in[7];
    P.p[2] = (const float*)d_in[8];  P.p[24 + 2] = (const float*)d_in[9];
    P.p[3] = (const float*)d_in[10]; P.p[24 + 3] = (const float*)d_in[11];
    P.p[4] = (const float*)d_in[12]; P.p[24 + 4] = (const float*)d_in[13];
    P.p[5] = (const float*)d_in[14]; P.p[24 + 5] = (const float*)d_in[15];
    const float* pW0 = (const float*)d_in[16]; const float* pb0 = (const float*)d_in[17];
    const float* pW1 = (const float*)d_in[18]; const float* pb1 = (const float*)d_in[19];
    const float* pW2 = (const float*)d_in[20]; const float* pb2 = (const float*)d_in[21];
    for (int s = 0; s < NSTEP; s++) {
        int m = 2 + s;
        P.p[m * 3 + 0] = pW0 + (size_t)s * LF * HF; P.p[24 + m * 3 + 0] = pb0 + (size_t)s * HF;
        P.p[m * 3 + 1] = pW1 + (size_t)s * HF * HF; P.p[24 + m * 3 + 1] = pb1 + (size_t)s * HF;
        P.p[m * 3 + 2] = pW2 + (size_t)s * HF * LF; P.p[24 + m * 3 + 2] = pb2 + (size_t)s * LF;
    }
    P.p[21] = (const float*)d_in[22]; P.p[24 + 21] = (const float*)d_in[23];
    P.p[22] = (const float*)d_in[24]; P.p[24 + 22] = (const float*)d_in[25];
    P.p[23] = (const float*)d_in[26]; P.p[24 + 23] = (const float*)d_in[27];

    float *pn = nullptr, *px = nullptr;
    int *pcnt = nullptr;
    unsigned int* pwq = nullptr;
    cudaGetSymbolAddress((void**)&pn, g_n);
    cudaGetSymbolAddress((void**)&px, g_x);
    cudaGetSymbolAddress((void**)&pcnt, g_cnt);
    cudaGetSymbolAddress((void**)&pwq, g_wq);

    static cudaStream_t s_csr = nullptr;
    static cudaEvent_t ev_fork = nullptr, ev_join = nullptr;
    if (!s_csr) {
        cudaStreamCreateWithFlags(&s_csr, cudaStreamNonBlocking);
        cudaEventCreateWithFlags(&ev_fork, cudaEventDisableTiming);
        cudaEventCreateWithFlags(&ev_join, cudaEventDisableTiming);
        cudaFuncSetAttribute((const void*)k_mlp_tc<3, 8, true, false, true, true>,
                             cudaFuncAttributeMaxDynamicSharedMemorySize, smem_bytes(3, 8));
        cudaFuncSetAttribute((const void*)k_mlp_tc<2, 8, false, false, false, false>,
                             cudaFuncAttributeMaxDynamicSharedMemorySize, smem_bytes(2, 8));
        cudaFuncSetAttribute((const void*)k_mlp_tc<64, 8, false, false, false, false>,
                             cudaFuncAttributeMaxDynamicSharedMemorySize, smem_bytes(64, 8));
        cudaFuncSetAttribute((const void*)k_mlp_tc<64, 1, false, true, false, false>,
                             cudaFuncAttributeMaxDynamicSharedMemorySize, smem_bytes(64, 1));
    }

    const int nt_edge = (NE + 191) / 192;
    const int nt_node = (NN + 191) / 192;

    // fork: CSR on side stream (+ work-queue counter reset)
    cudaEventRecord(ev_fork, 0);
    cudaStreamWaitEvent(s_csr, ev_fork, 0);

    cudaMemsetAsync(pcnt, 0, NN * sizeof(int), s_csr);
    cudaMemsetAsync(pwq, 0, 8 * sizeof(unsigned int), s_csr);
    k_hist<<<(NE + 255) / 256, 256, 0, s_csr>>>(receivers);
    k_scan1<<<NBLK, 256, 0, s_csr>>>();
    k_scan2<<<1, 256, 0, s_csr>>>();
    k_scan3<<<NBLK, 256, 0, s_csr>>>();
    k_scatter<<<(NE + 255) / 256, 256, 0, s_csr>>>(receivers, senders);
    cudaEventRecord(ev_join, s_csr);

    k_prep<<<dim3(64, 4), 256>>>(P);
    k_mlp_tc<2, 8, false, false, false, false><<<nt_node, 384, smem_bytes(2, 8)>>>(
        0, nodes, NN, nt_node, pn, nullptr, P.p[0], P.p[24 + 0]);

    cudaStreamWaitEvent(0, ev_join, 0);
    // edge encoder: 2-term split (output is fp16-quantized anyway), persistent
    k_mlp_tc<3, 8, true, false, true, true><<<148, 384, smem_bytes(3, 8)>>>(
        1, edges, NE, nt_edge, nullptr, nullptr, P.p[3], P.p[24 + 3]);

    for (int s = 0; s < NSTEP; s++) {
        k_message<<<888, 256>>>(s);
        k_mlp_tc<64, 8, false, false, false, false><<<nt_node, 384, smem_bytes(64, 8)>>>(
            2 + s, px, NN, nt_node, pn, nullptr, nullptr, nullptr);
    }

    k_mlp_tc<64, 1, false, true, false, false><<<nt_node, 384, smem_bytes(64, 1)>>>(
        7, pn, NN, nt_node, out, nodes, nullptr, nullptr);
}

// round 14
// speedup vs baseline: 1.1099x; 1.1099x over previous
#include <cuda_runtime.h>
#include <cuda_bf16.h>
#include <cuda_fp16.h>
#include <cstdint>

#define NN 50000
#define NE 1250000
#define LF 64
#define HF 128
#define NSTEP 5
#define EPSV 1e-6f
#define NBLK 196   // ceil(NN/256)

// ---------------- device scratch (static: no allocations allowed) -------------
__device__ __half g_e[(size_t)NE * LF];  // encoded edges, RECEIVER-SORTED, fp16
__device__ int    g_eid[NE];             // sorted slot -> edge id (scatter order)
__device__ int    g_send[NE];            // sender per sorted slot
__device__ int    g_off[NN + 1];
__device__ int    g_cnt[NN];
__device__ int    g_cur[NN];
__device__ int    g_bsum[256];
__device__ float  g_n[NN * LF];
__device__ float  g_x[NN * LF];

// split-precision fp16 weight fragments, hi/lo interleaved as uint4 {h0,h1,l0,l1}
__device__ uint4 g_fB0[8][4][16][32];   // layer1: K pad 64, N=128 (FIN=64 MLPs)
__device__ uint4 g_fB1[8][8][16][32];   // layer2: K=128, N=128
__device__ uint4 g_fB2[8][8][8][32];    // layer3: K=128, N pad 64
__device__ float g_b0[8][128], g_b1[8][128], g_b2[8][64];

struct WPtrs { const float* p[48]; };

// ---------------- helpers ------------------------------------------------------
// fp16 hi/lo split: residual after 11-bit hi is ~2^-22 -> 3-term MMA ~fp32-exact
__device__ __forceinline__ void split_pack(float v0, float v1, uint32_t& h, uint32_t& l) {
    __half2 hp = __floats2half2_rn(v0, v1);
    float2 hf = __half22float2(hp);
    __half2 lp = __floats2half2_rn(v0 - hf.x, v1 - hf.y);
    h = *(uint32_t*)&hp;
    l = *(uint32_t*)&lp;
}

__device__ __forceinline__ void mma16816(float* c, const uint32_t* a, uint32_t b0, uint32_t b1) {
    asm volatile(
        "mma.sync.aligned.m16n8k16.row.col.f32.f16.f16.f32 "
        "{%0,%1,%2,%3}, {%4,%5,%6,%7}, {%8,%9}, {%0,%1,%2,%3};"
        : "+f"(c[0]), "+f"(c[1]), "+f"(c[2]), "+f"(c[3])
        : "r"(a[0]), "r"(a[1]), "r"(a[2]), "r"(a[3]), "r"(b0), "r"(b1));
}

// 3-term split MMA: C += Ah*Bh + Ah*Bl + Al*Bh  (~fp32-exact)
__device__ __forceinline__ void mma3(float* c, const uint32_t* ah, const uint32_t* al, uint4 b) {
    mma16816(c, ah, b.x, b.y);
    mma16816(c, ah, b.z, b.w);
    mma16816(c, al, b.x, b.y);
}
// 2-term split MMA: C += Ah*Bh + Ah*Bl  (drops Al*Bh — edge encoder only,
// whose output is fp16-quantized (2^-11) anyway)
__device__ __forceinline__ void mma2(float* c, const uint32_t* ah, uint4 b) {
    mma16816(c, ah, b.x, b.y);
    mma16816(c, ah, b.z, b.w);
}

// ---------------- weight fragment + bias prep (single kernel) ------------------
__global__ void k_prep(WPtrs P) {
    const int L = blockIdx.y;
    if (L == 3) {
        for (int idx = blockIdx.x * 256 + threadIdx.x; idx < 16 * 128 + 8 * 64; idx += gridDim.x * 256) {
            if (idx < 8 * 128) {
                int m = idx >> 7, j = idx & 127;
                g_b0[m][j] = P.p[24 + m * 3 + 0][j];
            } else if (idx < 16 * 128) {
                int t = idx - 1024;
                int m = t >> 7, j = t & 127;
                g_b1[m][j] = P.p[24 + m * 3 + 1][j];
            } else {
                int t = idx - 2048;
                int m = t >> 6, j = t & 63;
                int Nr = (m == 7) ? 2 : 64;
                g_b2[m][j] = (j < Nr) ? P.p[24 + m * 3 + 2][j] : 0.f;
            }
        }
        return;
    }
    const int KT = (L == 0) ? 4 : 8;
    const int NT = (L == 2) ? 8 : 16;
    const int total = 8 * KT * NT * 32;
    for (int idx = blockIdx.x * 256 + threadIdx.x; idx < total; idx += gridDim.x * 256) {
        int lane = idx & 31;
        int r = idx >> 5;
        int nt = r % NT; r /= NT;
        int kt = r % KT;
        int m = r / KT;
        int K = (L == 0) ? (m == 0 ? 2 : (m == 1 ? 3 : 64)) : 128;
        int N = (L == 2) ? (m == 7 ? 2 : 64) : 128;
        const float* W = P.p[m * 3 + L];
        int k0 = kt * 16 + 2 * (lane & 3);
        int n  = nt * 8 + (lane >> 2);
        float v[4];
        #pragma unroll
        for (int j = 0; j < 4; j++) {
            int k = k0 + (j >> 1) * 8 + (j & 1);
            v[j] = (k < K && n < N) ? W[k * N + n] : 0.f;
        }
        uint32_t h0, l0, h1, l1;
        split_pack(v[0], v[1], h0, l0);
        split_pack(v[2], v[3], h1, l1);
        uint4 f = make_uint4(h0, h1, l0, l1);
        if (L == 0)      g_fB0[m][kt][nt][lane] = f;
        else if (L == 1) g_fB1[m][kt][nt][lane] = f;
        else             g_fB2[m][kt][nt][lane] = f;
    }
}

// ---------------- fused 3-layer MLP, register-resident mma.sync ----------------
// 384 threads = 12 warps, tile = 192 rows (16 per warp).
// FIN<=4: layer 1 scalar fp32 (exact). EHALF: write output as fp16 to g_e.
// TWO: 2-term split on layers 2/3 (edge encoder only; output fp16 anyway).
template <int FIN, int NT3, bool GATHER, bool MASK, bool EHALF, bool TWO>
__global__ void __launch_bounds__(384, 1) k_mlp_tc(
    int mlp, const float* __restrict__ xin, int nrows, int ntiles,
    float* __restrict__ out, const float* __restrict__ msrc,
    const float* __restrict__ W0raw, const float* __restrict__ b0raw)
{
    constexpr bool SC1 = (FIN <= 4);
    extern __shared__ char smraw[];
    char* pp = smraw;
    float* sw0 = nullptr;
    uint4* s0 = nullptr;
    if constexpr (SC1) { sw0 = (float*)pp; pp += FIN * 128 * sizeof(float); }
    else { s0 = (uint4*)pp; pp += 4 * 16 * 32 * sizeof(uint4); }
    uint4* s1 = (uint4*)pp; pp += 8 * 16 * 32 * sizeof(uint4);
    uint4* s2 = (uint4*)pp; pp += 8 * NT3 * 32 * sizeof(uint4);
    float* sb0 = (float*)pp; pp += 128 * sizeof(float);
    float* sb1 = (float*)pp; pp += 128 * sizeof(float);
    float* sb2 = (float*)pp;

    const int tid = threadIdx.x;
    {
        if constexpr (SC1) {
            for (int i = tid; i < FIN * 128; i += 384) sw0[i] = __ldg(W0raw + i);
            if (tid < 128) sb0[tid] = __ldg(b0raw + tid);
        } else {
            const uint4* f0 = (const uint4*)g_fB0[mlp];
            for (int i = tid; i < 4 * 16 * 32; i += 384) s0[i] = f0[i];
            if (tid < 128) sb0[tid] = g_b0[mlp][tid];
        }
        const uint4* f1 = (const uint4*)g_fB1[mlp];
        for (int i = tid; i < 8 * 16 * 32; i += 384) s1[i] = f1[i];
        for (int i = tid; i < 8 * NT3 * 32; i += 384) {
            int lane = i & 31, t = i >> 5;
            int nt = t % NT3, kt = t / NT3;
            s2[i] = g_fB2[mlp][kt][nt][lane];
        }
        if (tid >= 128 && tid < 256) sb1[tid - 128] = g_b1[mlp][tid - 128];
        if (tid >= 256 && tid < 320) sb2[tid - 256] = g_b2[mlp][tid - 256];
    }
    __syncthreads();

    const int lane = tid & 31, w = tid >> 5;
    const int lr  = lane >> 2;
    const int lc2 = 2 * (lane & 3);

    for (int tile = blockIdx.x; tile < ntiles; tile += gridDim.x) {
        const int r0 = tile * 192 + w * 16 + lr;
        const int r1 = r0 + 8;

        float C1[16][4];
        #pragma unroll
        for (int nt = 0; nt < 16; nt++) {
            float2 b = *(const float2*)&sb0[nt * 8 + lc2];
            C1[nt][0] = b.x; C1[nt][1] = b.y; C1[nt][2] = b.x; C1[nt][3] = b.y;
        }

        if constexpr (SC1) {
            float x0[FIN], x1[FIN];
            #pragma unroll
            for (int k = 0; k < FIN; k++) { x0[k] = 0.f; x1[k] = 0.f; }
            if (r0 < nrows) {
                int s = GATHER ? __ldg(&g_eid[r0]) : r0;
                #pragma unroll
                for (int k = 0; k < FIN; k++) x0[k] = __ldg(xin + (size_t)s * FIN + k);
            }
            if (r1 < nrows) {
                int s = GATHER ? __ldg(&g_eid[r1]) : r1;
                #pragma unroll
                for (int k = 0; k < FIN; k++) x1[k] = __ldg(xin + (size_t)s * FIN + k);
            }
            #pragma unroll
            for (int nt = 0; nt < 16; nt++) {
                int c = nt * 8 + lc2;
                #pragma unroll
                for (int k = 0; k < FIN; k++) {
                    float2 wv = *(const float2*)&sw0[k * 128 + c];
                    C1[nt][0] = fmaf(x0[k], wv.x, C1[nt][0]);
                    C1[nt][1] = fmaf(x0[k], wv.y, C1[nt][1]);
                    C1[nt][2] = fmaf(x1[k], wv.x, C1[nt][2]);
                    C1[nt][3] = fmaf(x1[k], wv.y, C1[nt][3]);
                }
            }
        } else {
            uint32_t a1h[4][4], a1l[4][4];
            const float* x0 = (r0 < nrows) ? xin + (size_t)r0 * 64 : nullptr;
            const float* x1 = (r1 < nrows) ? xin + (size_t)r1 * 64 : nullptr;
            #pragma unroll
            for (int kt = 0; kt < 4; kt++) {
                int ks = kt * 16 + lc2;
                float2 p00 = x0 ? *(const float2*)(x0 + ks)     : make_float2(0.f, 0.f);
                float2 p10 = x1 ? *(const float2*)(x1 + ks)     : make_float2(0.f, 0.f);
                float2 p01 = x0 ? *(const float2*)(x0 + ks + 8) : make_float2(0.f, 0.f);
                float2 p11 = x1 ? *(const float2*)(x1 + ks + 8) : make_float2(0.f, 0.f);
                split_pack(p00.x, p00.y, a1h[kt][0], a1l[kt][0]);
                split_pack(p10.x, p10.y, a1h[kt][1], a1l[kt][1]);
                split_pack(p01.x, p01.y, a1h[kt][2], a1l[kt][2]);
                split_pack(p11.x, p11.y, a1h[kt][3], a1l[kt][3]);
            }
            #pragma unroll
            for (int kt = 0; kt < 4; kt++) {
                #pragma unroll
                for (int nt = 0; nt < 16; nt++)
                    mma3(C1[nt], a1h[kt], a1l[kt], s0[(kt * 16 + nt) * 32 + lane]);
            }
        }

        // ---- relu + split -> layer-2 A fragments ----
        uint32_t a2h[8][4], a2l[8][4];
        #pragma unroll
        for (int nt = 0; nt < 16; nt++) {
            float c0 = fmaxf(C1[nt][0], 0.f), c1 = fmaxf(C1[nt][1], 0.f);
            float c2 = fmaxf(C1[nt][2], 0.f), c3 = fmaxf(C1[nt][3], 0.f);
            int j = nt >> 1, o = (nt & 1) * 2;
            split_pack(c0, c1, a2h[j][o],     a2l[j][o]);
            split_pack(c2, c3, a2h[j][o + 1], a2l[j][o + 1]);
        }

        // ---- layer 2 ----
        float C2[16][4];
        #pragma unroll
        for (int nt = 0; nt < 16; nt++) {
            float2 b = *(const float2*)&sb1[nt * 8 + lc2];
            C2[nt][0] = b.x; C2[nt][1] = b.y; C2[nt][2] = b.x; C2[nt][3] = b.y;
        }
        #pragma unroll
        for (int kt = 0; kt < 8; kt++) {
            #pragma unroll
            for (int nt = 0; nt < 16; nt++) {
                if constexpr (TWO) mma2(C2[nt], a2h[kt], s1[(kt * 16 + nt) * 32 + lane]);
                else               mma3(C2[nt], a2h[kt], a2l[kt], s1[(kt * 16 + nt) * 32 + lane]);
            }
        }

        // ---- relu + split -> layer-3 A fragments ----
        uint32_t a3h[8][4], a3l[8][4];
        #pragma unroll
        for (int nt = 0; nt < 16; nt++) {
            float c0 = fmaxf(C2[nt][0], 0.f), c1 = fmaxf(C2[nt][1], 0.f);
            float c2 = fmaxf(C2[nt][2], 0.f), c3 = fmaxf(C2[nt][3], 0.f);
            int j = nt >> 1, o = (nt & 1) * 2;
            if constexpr (TWO) {
                __half2 hp = __floats2half2_rn(c0, c1);
                a3h[j][o] = *(uint32_t*)&hp;
                __half2 hp2 = __floats2half2_rn(c2, c3);
                a3h[j][o + 1] = *(uint32_t*)&hp2;
            } else {
                split_pack(c0, c1, a3h[j][o],     a3l[j][o]);
                split_pack(c2, c3, a3h[j][o + 1], a3l[j][o + 1]);
            }
        }

        // ---- layer 3 (linear) ----
        float C3[NT3][4];
        #pragma unroll
        for (int nt = 0; nt < NT3; nt++) {
            float2 b = *(const float2*)&sb2[nt * 8 + lc2];
            C3[nt][0] = b.x; C3[nt][1] = b.y; C3[nt][2] = b.x; C3[nt][3] = b.y;
        }
        #pragma unroll
        for (int kt = 0; kt < 8; kt++) {
            #pragma unroll
            for (int nt = 0; nt < NT3; nt++) {
                if constexpr (TWO) mma2(C3[nt], a3h[kt], s2[(kt * NT3 + nt) * 32 + lane]);
                else               mma3(C3[nt], a3h[kt], a3l[kt], s2[(kt * NT3 + nt) * 32 + lane]);
            }
        }

        // ---- store ----
        if constexpr (EHALF) {
            #pragma unroll
            for (int nt = 0; nt < 8; nt++) {
                int ci = nt * 4 + (lane & 3);
                if (r0 < nrows)
                    *(__half2*)&g_e[(size_t)r0 * 64 + 2 * ci] = __floats2half2_rn(C3[nt][0], C3[nt][1]);
                if (r1 < nrows)
                    *(__half2*)&g_e[(size_t)r1 * 64 + 2 * ci] = __floats2half2_rn(C3[nt][2], C3[nt][3]);
            }
        } else if (NT3 == 8) {
            #pragma unroll
            for (int nt = 0; nt < 8; nt++) {
                if (r0 < nrows) *(float2*)&out[(size_t)r0 * 64 + nt * 8 + lc2] = make_float2(C3[nt][0], C3[nt][1]);
                if (r1 < nrows) *(float2*)&out[(size_t)r1 * 64 + nt * 8 + lc2] = make_float2(C3[nt][2], C3[nt][3]);
            }
        } else {  // FOUT = 2 decoder
            if ((lane & 3) == 0) {
                if (r0 < nrows) {
                    float m0 = 1.f;
                    if (MASK) {
                        float2 nv = *(const float2*)&msrc[(size_t)r0 * 2];
                        m0 = ((fabsf(nv.x) + fabsf(nv.y)) != 0.f) ? 1.f : 0.f;
                    }
                    *(float2*)&out[(size_t)r0 * 2] = make_float2(C3[0][0] * m0, C3[0][1] * m0);
                }
                if (r1 < nrows) {
                    float m1 = 1.f;
                    if (MASK) {
                        float2 nv = *(const float2*)&msrc[(size_t)r1 * 2];
                        m1 = ((fabsf(nv.x) + fabsf(nv.y)) != 0.f) ? 1.f : 0.f;
                    }
                    *(float2*)&out[(size_t)r1 * 2] = make_float2(C3[0][2] * m1, C3[0][3] * m1);
                }
            }
        }
    }
}

constexpr int smem_bytes(int FIN, int NT3) {
    return ((FIN <= 4) ? (FIN * 128 * 4) : (4 * 16 * 32 * 16))
         + (8 * 16 * 32 + 8 * NT3 * 32) * 16
         + (128 + 128 + 64) * 4;
}

// ---------------- CSR build ----------------------------------------------------
__global__ void k_hist(const int* __restrict__ recv) {
    int i = blockIdx.x * blockDim.x + threadIdx.x;
    if (i < NE) atomicAdd(&g_cnt[recv[i]], 1);
}
__global__ void k_scan1() {
    __shared__ int s[256];
    int t = threadIdx.x;
    int i = blockIdx.x * 256 + t;
    int v = (i < NN) ? g_cnt[i] : 0;
    s[t] = v;
    __syncthreads();
    #pragma unroll
    for (int d = 1; d < 256; d <<= 1) {
        int y = (t >= d) ? s[t - d] : 0;
        __syncthreads();
        s[t] += y;
        __syncthreads();
    }
    if (i < NN) g_off[i] = s[t] - v;
    if (t == 255) g_bsum[blockIdx.x] = s[255];
}
__global__ void k_scan2() {
    __shared__ int s[256];
    int t = threadIdx.x;
    int v = (t < NBLK) ? g_bsum[t] : 0;
    s[t] = v;
    __syncthreads();
    #pragma unroll
    for (int d = 1; d < 256; d <<= 1) {
        int y = (t >= d) ? s[t - d] : 0;
        __syncthreads();
        s[t] += y;
        __syncthreads();
    }
    if (t < NBLK) g_bsum[t] = s[t] - v;
    if (t == 255) g_off[NN] = s[255];
}
__global__ void k_scan3() {
    int i = blockIdx.x * 256 + threadIdx.x;
    if (i < NN) {
        int o = g_off[i] + g_bsum[i >> 8];
        g_off[i] = o;
        g_cur[i] = o;
    }
}
// scatter fills g_send directly (no per-segment sort: intra-segment order
// only perturbs FP summation order, ~ulp-level output variation)
__global__ void k_scatter(const int* __restrict__ recv, const int* __restrict__ senders) {
    int i = blockIdx.x * blockDim.x + threadIdx.x;
    if (i < NE) {
        int p = atomicAdd(&g_cur[recv[i]], 1);
        g_eid[p] = i;
        g_send[p] = senders[i];
    }
}

// ---------------- GEN message + softmax aggregation (no-max, MLP=8) ------------
// Static warp-per-receiver, 4-wide pipelined. 64-thread blocks (2 warps): the
// per-block tail is max-of-2 degrees instead of max-of-8, and the HW scheduler
// back-fills SMs from the 25k-block pool — free dynamic load balancing.
__global__ void __launch_bounds__(64) k_message() {
    int lane = threadIdx.x & 31;
    int r = blockIdx.x * 2 + (threadIdx.x >> 5);
    if (r >= NN) return;
    int o = g_off[r], e = g_off[r + 1];

    float S0 = 0.f, S1 = 0.f, W0 = 0.f, W1 = 0.f;
    const int fo = 2 * lane;

    int p = o;
    for (; p + 4 <= e; p += 4) {
        int s0 = __ldg(&g_send[p]);
        int s1 = __ldg(&g_send[p + 1]);
        int s2 = __ldg(&g_send[p + 2]);
        int s3 = __ldg(&g_send[p + 3]);
        __half2 e0 = __ldg((const __half2*)&g_e[(size_t)(p)     * 64 + fo]);
        __half2 e1 = __ldg((const __half2*)&g_e[(size_t)(p + 1) * 64 + fo]);
        __half2 e2 = __ldg((const __half2*)&g_e[(size_t)(p + 2) * 64 + fo]);
        __half2 e3 = __ldg((const __half2*)&g_e[(size_t)(p + 3) * 64 + fo]);
        float2 n0 = __ldg((const float2*)&g_n[(size_t)s0 * 64 + fo]);
        float2 n1 = __ldg((const float2*)&g_n[(size_t)s1 * 64 + fo]);
        float2 n2 = __ldg((const float2*)&g_n[(size_t)s2 * 64 + fo]);
        float2 n3 = __ldg((const float2*)&g_n[(size_t)s3 * 64 + fo]);

        float2 f0 = __half22float2(e0), f1 = __half22float2(e1);
        float2 f2 = __half22float2(e2), f3 = __half22float2(e3);
        float ma0 = fmaxf(n0.x + f0.x, 0.f) + EPSV, mb0 = fmaxf(n0.y + f0.y, 0.f) + EPSV;
        float ma1 = fmaxf(n1.x + f1.x, 0.f) + EPSV, mb1 = fmaxf(n1.y + f1.y, 0.f) + EPSV;
        float ma2 = fmaxf(n2.x + f2.x, 0.f) + EPSV, mb2 = fmaxf(n2.y + f2.y, 0.f) + EPSV;
        float ma3 = fmaxf(n3.x + f3.x, 0.f) + EPSV, mb3 = fmaxf(n3.y + f3.y, 0.f) + EPSV;
        float ta0 = __expf(ma0), tb0 = __expf(mb0);
        float ta1 = __expf(ma1), tb1 = __expf(mb1);
        float ta2 = __expf(ma2), tb2 = __expf(mb2);
        float ta3 = __expf(ma3), tb3 = __expf(mb3);
        S0 += (ta0 + ta1) + (ta2 + ta3);
        S1 += (tb0 + tb1) + (tb2 + tb3);
        W0 += fmaf(ta0, ma0, ta1 * ma1) + fmaf(ta2, ma2, ta3 * ma3);
        W1 += fmaf(tb0, mb0, tb1 * mb1) + fmaf(tb2, mb2, tb3 * mb3);
    }
    for (; p < e; p++) {
        int s = __ldg(&g_send[p]);
        __half2 eh = __ldg((const __half2*)&g_e[(size_t)p * 64 + fo]);
        float2 nv = __ldg((const float2*)&g_n[(size_t)s * 64 + fo]);
        float2 ec = __half22float2(eh);
        float m0 = fmaxf(nv.x + ec.x, 0.f) + EPSV;
        float m1 = fmaxf(nv.y + ec.y, 0.f) + EPSV;
        float t0 = __expf(m0);
        float t1 = __expf(m1);
        S0 += t0; W0 = fmaf(t0, m0, W0);
        S1 += t1; W1 = fmaf(t1, m1, W1);
    }

    float2 ns = *(const float2*)&g_n[(size_t)r * 64 + fo];
    float a0 = (e > o) ? (W0 / S0) : 0.f;
    float a1 = (e > o) ? (W1 / S1) : 0.f;
    *(float2*)&g_x[(size_t)r * 64 + fo] = make_float2(ns.x + a0, ns.y + a1);
}

// ---------------- host launcher ------------------------------------------------
extern "C" void kernel_launch(void* const* d_in, const int* in_sizes, int n_in,
                              void* d_out, int out_size) {
    (void)in_sizes; (void)n_in; (void)out_size;

    const float* nodes     = (const float*)d_in[0];
    const float* edges     = (const float*)d_in[1];
    const int*   senders   = (const int*)d_in[2];
    const int*   receivers = (const int*)d_in[3];
    float* out = (float*)d_out;

    WPtrs P;
    P.p[0] = (const float*)d_in[4];  P.p[24 + 0] = (const float*)d_in[5];
    P.p[1] = (const float*)d_in[6];  P.p[24 + 1] = (const float*)d_in[7];
    P.p[2] = (const float*)d_in[8];  P.p[24 + 2] = (const float*)d_in[9];
    P.p[3] = (const float*)d_in[10]; P.p[24 + 3] = (const float*)d_in[11];
    P.p[4] = (const float*)d_in[12]; P.p[24 + 4] = (const float*)d_in[13];
    P.p[5] = (const float*)d_in[14]; P.p[24 + 5] = (const float*)d_in[15];
    const float* pW0 = (const float*)d_in[16]; const float* pb0 = (const float*)d_in[17];
    const float* pW1 = (const float*)d_in[18]; const float* pb1 = (const float*)d_in[19];
    const float* pW2 = (const float*)d_in[20]; const float* pb2 = (const float*)d_in[21];
    for (int s = 0; s < NSTEP; s++) {
        int m = 2 + s;
        P.p[m * 3 + 0] = pW0 + (size_t)s * LF * HF; P.p[24 + m * 3 + 0] = pb0 + (size_t)s * HF;
        P.p[m * 3 + 1] = pW1 + (size_t)s * HF * HF; P.p[24 + m * 3 + 1] = pb1 + (size_t)s * HF;
        P.p[m * 3 + 2] = pW2 + (size_t)s * HF * LF; P.p[24 + m * 3 + 2] = pb2 + (size_t)s * LF;
    }
    P.p[21] = (const float*)d_in[22]; P.p[24 + 21] = (const float*)d_in[23];
    P.p[22] = (const float*)d_in[24]; P.p[24 + 22] = (const float*)d_in[25];
    P.p[23] = (const float*)d_in[26]; P.p[24 + 23] = (const float*)d_in[27];

    float *pn = nullptr, *px = nullptr;
    int* pcnt = nullptr;
    cudaGetSymbolAddress((void**)&pn, g_n);
    cudaGetSymbolAddress((void**)&px, g_x);
    cudaGetSymbolAddress((void**)&pcnt, g_cnt);

    static cudaStream_t s_csr = nullptr;
    static cudaEvent_t ev_fork = nullptr, ev_join = nullptr;
    if (!s_csr) {
        cudaStreamCreateWithFlags(&s_csr, cudaStreamNonBlocking);
        cudaEventCreateWithFlags(&ev_fork, cudaEventDisableTiming);
        cudaEventCreateWithFlags(&ev_join, cudaEventDisableTiming);
        cudaFuncSetAttribute((const void*)k_mlp_tc<3, 8, true, false, true, true>,
                             cudaFuncAttributeMaxDynamicSharedMemorySize, smem_bytes(3, 8));
        cudaFuncSetAttribute((const void*)k_mlp_tc<2, 8, false, false, false, false>,
                             cudaFuncAttributeMaxDynamicSharedMemorySize, smem_bytes(2, 8));
        cudaFuncSetAttribute((const void*)k_mlp_tc<64, 8, false, false, false, false>,
                             cudaFuncAttributeMaxDynamicSharedMemorySize, smem_bytes(64, 8));
        cudaFuncSetAttribute((const void*)k_mlp_tc<64, 1, false, true, false, false>,
                             cudaFuncAttributeMaxDynamicSharedMemorySize, smem_bytes(64, 1));
    }

    const int nt_edge = (NE + 191) / 192;
    const int nt_node = (NN + 191) / 192;

    // fork: CSR on side stream
    cudaEventRecord(ev_fork, 0);
    cudaStreamWaitEvent(s_csr, ev_fork, 0);

    cudaMemsetAsync(pcnt, 0, NN * sizeof(int), s_csr);
    k_hist<<<(NE + 255) / 256, 256, 0, s_csr>>>(receivers);
    k_scan1<<<NBLK, 256, 0, s_csr>>>();
    k_scan2<<<1, 256, 0, s_csr>>>();
    k_scan3<<<NBLK, 256, 0, s_csr>>>();
    k_scatter<<<(NE + 255) / 256, 256, 0, s_csr>>>(receivers, senders);
    cudaEventRecord(ev_join, s_csr);

    k_prep<<<dim3(64, 4), 256>>>(P);
    k_mlp_tc<2, 8, false, false, false, false><<<nt_node, 384, smem_bytes(2, 8)>>>(
        0, nodes, NN, nt_node, pn, nullptr, P.p[0], P.p[24 + 0]);

    cudaStreamWaitEvent(0, ev_join, 0);
    // edge encoder: 2-term split (output is fp16-quantized anyway), persistent
    k_mlp_tc<3, 8, true, false, true, true><<<148, 384, smem_bytes(3, 8)>>>(
        1, edges, NE, nt_edge, nullptr, nullptr, P.p[3], P.p[24 + 3]);

    for (int s = 0; s < NSTEP; s++) {
        k_message<<<(NN + 1) / 2, 64>>>();
        k_mlp_tc<64, 8, false, false, false, false><<<nt_node, 384, smem_bytes(64, 8)>>>(
            2 + s, px, NN, nt_node, pn, nullptr, nullptr, nullptr);
    }

    k_mlp_tc<64, 1, false, true, false, false><<<nt_node, 384, smem_bytes(64, 1)>>>(
        7, pn, NN, nt_node, out, nodes, nullptr, nullptr);
}